// round 12
// baseline (speedup 1.0000x reference)
#include <cuda_runtime.h>
#include <cuda_bf16.h>
#include <cstdint>
#include <math.h>

#define NPTS 8192
#define NMAT ((size_t)NPTS * (size_t)NPTS)
#define TS   512
#define QR   128                        /* rows per quarter-tile block */
#define NT   16
#define NPAIRS 136                      /* NT*(NT+1)/2 */
#define TILE_ELEMS ((size_t)TS * TS)
#define NSYMB (2 * NPAIRS * 4)          /* 1088 sym quarter blocks */

#define EPSV     0.05f
#define INV_EPS  20.0f
#define CLOGN    0.45054567f   /* eps * log(8192) */

// ---- scratch (static device memory; allocation-free) ----
__device__ __nv_bfloat16 g_Kxy[NMAT];
__device__ __nv_bfloat16 g_Kyx[NMAT];
__device__ __nv_bfloat16 g_Kxx[NPAIRS * TILE_ELEMS];  // packed lower-triangle tiles
__device__ __nv_bfloat16 g_Kyy[NPAIRS * TILE_ELEMS];

__device__ float g_Prow[2][NPTS][NT];      // row partials [xx|yy][row][Bslot]
__device__ float g_Pcol[4][2][NPTS][NT];   // col partials [quarter][xx|yy][col][Aslot]
__device__ float g_Pxy[2][NPTS][2];        // xy partials [f|g][row][colhalf]

__device__ float g_f[NPTS], g_g[NPTS], g_wf[NPTS], g_wg[NPTS];
__device__ float g_hx[2][NPTS], g_whx[2][NPTS];
__device__ float g_hy[2][NPTS], g_why[2][NPTS];
__device__ float g_cham[NPTS];

__device__ __forceinline__ float bf_lo(unsigned u){ return __uint_as_float(u << 16); }
__device__ __forceinline__ float bf_hi(unsigned u){ return __uint_as_float(u & 0xffff0000u); }

__device__ __forceinline__ void decode_pair(int p, int& A, int& B){
  int a = (int)((sqrtf(8.f * p + 1.f) - 1.f) * 0.5f);
  while ((a + 1) * (a + 2) / 2 <= p) a++;
  while (a * (a + 1) / 2 > p) a--;
  A = a; B = p - ((a * (a + 1)) >> 1);
}

__global__ void init_kernel(){
  int i = blockIdx.x * blockDim.x + threadIdx.x;
  if (i < NPTS){
    g_wf[i] = 1.f; g_wg[i] = 1.f;
    g_whx[0][i] = 1.f; g_whx[1][i] = 1.f;
    g_why[0][i] = 1.f; g_why[1][i] = 1.f;
    g_f[i] = 0.f; g_g[i] = 0.f;
    g_hx[0][i] = 0.f; g_hx[1][i] = 0.f;
    g_hy[0][i] = 0.f; g_hy[1][i] = 0.f;
  }
  int nrow = 2 * NPTS * NT;
  for (int j = i; j < nrow; j += gridDim.x * blockDim.x)
    (&g_Prow[0][0][0])[j] = 0.f;
  int ncol = 4 * 2 * NPTS * NT;
  for (int j = i; j < ncol; j += gridDim.x * blockDim.x)
    (&g_Pcol[0][0][0][0])[j] = 0.f;
}

// xy fills: one block per row. which: 0=Kxy  1=Kyx (+chamfer row mins)
__global__ void __launch_bounds__(256) fill_kernel(const float* __restrict__ Apts,
                                                   const float* __restrict__ Bpts,
                                                   int which){
  __nv_bfloat16* K = (which == 0) ? g_Kxy : g_Kyx;
  float* rowmin = (which == 1) ? g_cham : nullptr;

  int row = blockIdx.x;
  float4 ap = reinterpret_cast<const float4*>(Apts)[row];
  float na = ap.x*ap.x + ap.y*ap.y + ap.z*ap.z;
  float mn = INFINITY;
  unsigned* Kout = reinterpret_cast<unsigned*>(K + ((size_t)row << 13));
  const float4* Bv = reinterpret_cast<const float4*>(Bpts);

  for (int k = threadIdx.x; k < NPTS/2; k += 256){
    float4 b0 = Bv[2*k], b1 = Bv[2*k + 1];
    float d0 = fmaxf(na + (b0.x*b0.x + b0.y*b0.y + b0.z*b0.z)
                        - 2.f*(ap.x*b0.x + ap.y*b0.y + ap.z*b0.z), 0.f);
    float d1 = fmaxf(na + (b1.x*b1.x + b1.y*b1.y + b1.z*b1.z)
                        - 2.f*(ap.x*b1.x + ap.y*b1.y + ap.z*b1.z), 0.f);
    mn = fminf(mn, fminf(d0, d1));
    float e0 = __expf(-INV_EPS * sqrtf(d0 + 1e-12f));
    float e1 = __expf(-INV_EPS * sqrtf(d1 + 1e-12f));
    __nv_bfloat162 p = __floats2bfloat162_rn(e0, e1);
    Kout[k] = *reinterpret_cast<unsigned*>(&p);
  }

  if (rowmin){
    __shared__ float sredm[8];
    int lane = threadIdx.x & 31, wid = threadIdx.x >> 5;
    #pragma unroll
    for (int o = 16; o; o >>= 1) mn = fminf(mn, __shfl_xor_sync(0xffffffffu, mn, o));
    if (lane == 0) sredm[wid] = mn;
    __syncthreads();
    if (threadIdx.x == 0){
      float m = sredm[0];
      #pragma unroll
      for (int w = 1; w < 8; w++) m = fminf(m, sredm[w]);
      rowmin[row] = m;
    }
  }
}

// Packed symmetric fills: 8 tile-rows per block.
__global__ void __launch_bounds__(256) fill_sym_kernel(const float* __restrict__ xpts,
                                                       const float* __restrict__ ypts){
  __shared__ __align__(16) float4 sB[TS];
  int blk = blockIdx.x;
  int mat = (blk >= NPAIRS * 64) ? 1 : 0;
  if (mat) blk -= NPAIRS * 64;
  int p  = blk >> 6;
  int rr = (blk & 63) << 3;
  int A, B; decode_pair(p, A, B);

  const float* pts = mat ? ypts : xpts;
  __nv_bfloat16* out = (mat ? g_Kyy : g_Kxx) + (size_t)p * TILE_ELEMS;

  const float4* P4 = reinterpret_cast<const float4*>(pts);
  for (int i = threadIdx.x; i < TS; i += 256) sB[i] = P4[B * TS + i];
  __syncthreads();

  int lane = threadIdx.x & 31, wid = threadIdx.x >> 5;
  int r = rr + wid;
  float4 ap = P4[A * TS + r];
  float na = ap.x*ap.x + ap.y*ap.y + ap.z*ap.z;
  unsigned* orow = reinterpret_cast<unsigned*>(out + ((size_t)r << 9));

  #pragma unroll
  for (int c0 = 0; c0 < 8; c0++){
    int c = (c0 << 5) + lane;
    float4 b0 = sB[2*c], b1 = sB[2*c + 1];
    float d0 = fmaxf(na + (b0.x*b0.x + b0.y*b0.y + b0.z*b0.z)
                        - 2.f*(ap.x*b0.x + ap.y*b0.y + ap.z*b0.z), 0.f);
    float d1 = fmaxf(na + (b1.x*b1.x + b1.y*b1.y + b1.z*b1.z)
                        - 2.f*(ap.x*b1.x + ap.y*b1.y + ap.z*b1.z), 0.f);
    float e0 = __expf(-INV_EPS * sqrtf(d0 + 1e-12f));
    float e1 = __expf(-INV_EPS * sqrtf(d1 + 1e-12f));
    __nv_bfloat162 pk = __floats2bfloat162_rn(e0, e1);
    orow[c] = *reinterpret_cast<unsigned*>(&pk);
  }
}

// ---- finish device functions ----
// sym finish for step tf: 64 blocks' worth (blk 0..63), 16384 threads total.
__device__ __forceinline__ void sym_finish(int tf, int blk, int tid){
  int idx = blk * 256 + tid;      // 0..16383
  int mat = idx >> 13;
  int r   = idx & (NPTS - 1);
  const float4* Pr = reinterpret_cast<const float4*>(g_Prow[mat][r]);
  float4 a0 = Pr[0], a1 = Pr[1], a2 = Pr[2], a3 = Pr[3];
  float s = (a0.x+a0.y+a0.z+a0.w) + (a1.x+a1.y+a1.z+a1.w)
          + (a2.x+a2.y+a2.z+a2.w) + (a3.x+a3.y+a3.z+a3.w);
  #pragma unroll
  for (int qq = 0; qq < 4; qq++){
    const float4* Pc = reinterpret_cast<const float4*>(g_Pcol[qq][mat][r]);
    float4 c0 = Pc[0], c1 = Pc[1], c2 = Pc[2], c3 = Pc[3];
    s += (c0.x+c0.y+c0.z+c0.w) + (c1.x+c1.y+c1.z+c1.w)
       + (c2.x+c2.y+c2.z+c2.w) + (c3.x+c3.y+c3.z+c3.w);
  }
  s = fmaxf(s, 1e-35f);
  float val = CLOGN - EPSV * __logf(s);
  int out = tf & 1;
  if (mat == 0){ g_hx[out][r] = val; g_whx[out][r] = 8192.f / s; }
  else         { g_hy[out][r] = val; g_why[out][r] = 8192.f / s; }
}

// xy finish for step t: 32 blocks' worth (blk 0..31), 8192 threads total.
__device__ __forceinline__ void xy_finish(int t, int blk, int tid){
  int r = blk * 256 + tid;        // 0..8191
  int side = t & 1;               // 0: f just written, 1: g
  float2 pp = *reinterpret_cast<const float2*>(g_Pxy[side][r]);
  float s = fmaxf(pp.x + pp.y, 1e-35f);
  float val = CLOGN - EPSV * __logf(s);
  if (side == 0){ g_f[r] = val; g_wf[r] = 8192.f / s; }
  else          { g_g[r] = val; g_wg[r] = 8192.f / s; }
}

// K1(t): blocks 0..1023 = xy step(t); blocks 1024..1087 = sym finish(t-1).
__global__ void __launch_bounds__(256) step1_kernel(int t){
  __shared__ __align__(16) float sbuf[4096];
  int tid = threadIdx.x, lane = tid & 31, wid = tid >> 5;
  int b = blockIdx.x;
  bool even = (t & 1) == 0;

  if (b >= 1024){
    if (t > 0) sym_finish(t - 1, b - 1024, tid);
    return;
  }

  // ---------------- xy chain: 16 rows x 4096 cols ----------------
  const __nv_bfloat16* K = even ? g_Kxy : g_Kyx;
  const float* win  = even ? g_wg : g_wf;
  float (*Pout)[2]  = even ? g_Pxy[0] : g_Pxy[1];
  int rowgrp = b >> 1, half = b & 1;
  int cbase = half << 12;

  float* sw = sbuf;   // 4096 w values for this column half
  for (int i = tid; i < 1024; i += 256)
    reinterpret_cast<float4*>(sw)[i] = reinterpret_cast<const float4*>(win + cbase)[i];
  __syncthreads();

  int row0 = (rowgrp << 4) + (wid << 1);
  const uint4* K0 = reinterpret_cast<const uint4*>(K + ((size_t)row0 << 13) + cbase);
  const uint4* K1 = reinterpret_cast<const uint4*>(K + ((size_t)(row0 + 1) << 13) + cbase);
  float s0 = 0.f, s1 = 0.f;
  #pragma unroll 4
  for (int it = lane; it < 512; it += 32){
    uint4 a = K0[it];
    uint4 c = K1[it];
    const float4* vp = reinterpret_cast<const float4*>(sw + (it << 3));
    float4 v0 = vp[0], v1 = vp[1];
    s0 += bf_lo(a.x)*v0.x + bf_hi(a.x)*v0.y + bf_lo(a.y)*v0.z + bf_hi(a.y)*v0.w
        + bf_lo(a.z)*v1.x + bf_hi(a.z)*v1.y + bf_lo(a.w)*v1.z + bf_hi(a.w)*v1.w;
    s1 += bf_lo(c.x)*v0.x + bf_hi(c.x)*v0.y + bf_lo(c.y)*v0.z + bf_hi(c.y)*v0.w
        + bf_lo(c.z)*v1.x + bf_hi(c.z)*v1.y + bf_lo(c.w)*v1.z + bf_hi(c.w)*v1.w;
  }
  #pragma unroll
  for (int o = 16; o; o >>= 1){
    s0 += __shfl_xor_sync(0xffffffffu, s0, o);
    s1 += __shfl_xor_sync(0xffffffffu, s1, o);
  }
  if (lane == 0){
    Pout[row0][half]     = s0;
    Pout[row0 + 1][half] = s1;
  }
}

// K2(t): blocks 0..NSYMB-1 = sym quarter-tile step(t); blocks NSYMB.. = xy finish(t).
__global__ void __launch_bounds__(256) step2_kernel(int t){
  __shared__ __align__(16) float sbuf[4736];
  int tid = threadIdx.x, lane = tid & 31, wid = tid >> 5;
  int b = blockIdx.x;

  if (b >= NSYMB){
    xy_finish(t, b - NSYMB, tid);
    return;
  }

  // ------------- symmetric chains: quarter-tiles -------------
  int mat = (b >= NPAIRS * 4) ? 1 : 0;
  int q   = mat ? b - NPAIRS * 4 : b;
  int p   = q >> 2, quarter = q & 3;
  int A, B; decode_pair(p, A, B);
  bool diag = (A == B);

  const __nv_bfloat16* Ktile = (mat ? g_Kyy : g_Kxx)
                             + (size_t)p * TILE_ELEMS + ((size_t)(quarter * QR) << 9);
  int in = ((t & 1) ^ 1);
  const float* win = mat ? g_why[in] : g_whx[in];

  float* wcol = sbuf;             // 512 (columns = B block)
  float* wrow = sbuf + TS;        // 128 (this quarter's rows)
  float* cs   = sbuf + TS + QR;   // 8 * 512 staging

  for (int i = tid; i < TS; i += 256) wcol[i] = win[B * TS + i];
  if (tid < QR) wrow[tid] = win[A * TS + quarter * QR + tid];
  __syncthreads();

  float4 acc[4];
  #pragma unroll
  for (int i = 0; i < 4; i++) acc[i] = make_float4(0.f, 0.f, 0.f, 0.f);

  for (int r = wid; r < QR; r += 8){
    const uint4* Kr = reinterpret_cast<const uint4*>(Ktile + ((size_t)r << 9));
    float wr = wrow[r];
    float rd = 0.f;
    #pragma unroll
    for (int i = 0; i < 2; i++){
      uint4 kk = Kr[(i << 5) + lane];
      const float4* wp = reinterpret_cast<const float4*>(wcol + (i << 8) + (lane << 3));
      float4 w0 = wp[0], w1 = wp[1];
      float k0 = bf_lo(kk.x), k1 = bf_hi(kk.x), k2 = bf_lo(kk.y), k3 = bf_hi(kk.y);
      float k4 = bf_lo(kk.z), k5 = bf_hi(kk.z), k6 = bf_lo(kk.w), k7 = bf_hi(kk.w);
      rd += k0*w0.x + k1*w0.y + k2*w0.z + k3*w0.w
          + k4*w1.x + k5*w1.y + k6*w1.z + k7*w1.w;
      if (!diag){
        acc[2*i].x   += k0 * wr;  acc[2*i].y   += k1 * wr;
        acc[2*i].z   += k2 * wr;  acc[2*i].w   += k3 * wr;
        acc[2*i+1].x += k4 * wr;  acc[2*i+1].y += k5 * wr;
        acc[2*i+1].z += k6 * wr;  acc[2*i+1].w += k7 * wr;
      }
    }
    #pragma unroll
    for (int o = 16; o; o >>= 1) rd += __shfl_xor_sync(0xffffffffu, rd, o);
    if (lane == 0)
      g_Prow[mat][A * TS + quarter * QR + r][B] = rd;
  }

  if (!diag){
    #pragma unroll
    for (int i = 0; i < 2; i++){
      *reinterpret_cast<float4*>(cs + wid * TS + (i << 8) + (lane << 3))     = acc[2*i];
      *reinterpret_cast<float4*>(cs + wid * TS + (i << 8) + (lane << 3) + 4) = acc[2*i+1];
    }
    __syncthreads();
    for (int c = tid; c < TS; c += 256){
      float s = 0.f;
      #pragma unroll
      for (int w = 0; w < 8; w++) s += cs[w * TS + c];
      g_Pcol[quarter][mat][B * TS + c][A] = s;
    }
  }
}

// Standalone sym finish for the last step (t = 99).
__global__ void __launch_bounds__(256) symfin_kernel(int tf){
  sym_finish(tf, blockIdx.x, threadIdx.x);
}

__global__ void final_kernel(float* out){
  __shared__ float sred[8];
  int tid = threadIdx.x, lane = tid & 31, wid = tid >> 5;
  const float* arrs[7] = { g_f, g_g, g_hx[0], g_hx[1], g_hy[0], g_hy[1], g_cham };
  float totals[7];
  for (int a = 0; a < 7; a++){
    float s = 0.f;
    for (int i = tid; i < NPTS; i += 256) s += arrs[a][i];
    #pragma unroll
    for (int o = 16; o; o >>= 1) s += __shfl_xor_sync(0xffffffffu, s, o);
    __syncthreads();
    if (lane == 0) sred[wid] = s;
    __syncthreads();
    if (tid == 0){
      float tt = 0.f;
      #pragma unroll
      for (int w = 0; w < 8; w++) tt += sred[w];
      totals[a] = tt;
    }
  }
  if (tid == 0){
    const float invN = 1.f / (float)NPTS;
    float ot_xy = (totals[0] + totals[1]) * invN;
    float ot_xx = (totals[2] + totals[3]) * invN;
    float ot_yy = (totals[4] + totals[5]) * invN;
    float cham  = totals[6] * invN;
    float emd = ot_xy - 0.5f * ot_xx - 0.5f * ot_yy;
    out[0] = 0.2f * cham + 0.8f * emd;
  }
}

extern "C" void kernel_launch(void* const* d_in, const int* in_sizes, int n_in,
                              void* d_out, int out_size){
  const float* pred = (const float*)d_in[0];
  const float* gt   = (const float*)d_in[1];
  float* out = (float*)d_out;

  init_kernel<<<256, 256>>>();
  fill_kernel<<<NPTS, 256>>>(pred, gt,   0);            // Kxy
  fill_kernel<<<NPTS, 256>>>(gt,   pred, 1);            // Kyx + chamfer row mins
  fill_sym_kernel<<<2 * NPAIRS * 64, 256>>>(pred, gt);  // packed Kxx + Kyy

  for (int t = 0; t < 100; t++){
    step1_kernel<<<1024 + 64, 256>>>(t);     // xy step(t) + sym finish(t-1)
    step2_kernel<<<NSYMB + 32, 256>>>(t);    // sym step(t) + xy finish(t)
  }

  symfin_kernel<<<64, 256>>>(99);            // sym finish of last step
  final_kernel<<<1, 256>>>(out);
}

// round 13
// speedup vs baseline: 1.2460x; 1.2460x over previous
#include <cuda_runtime.h>
#include <cuda_bf16.h>
#include <cstdint>
#include <math.h>

#define NPTS 8192
#define NMAT ((size_t)NPTS * (size_t)NPTS)
#define TS   512
#define QR   128                        /* rows per quarter-tile block */
#define NT   16
#define NPAIRS 136                      /* NT*(NT+1)/2 */
#define TILE_ELEMS ((size_t)TS * TS)
#define NSYMB (2 * NPAIRS * 4)          /* 1088 sym quarter blocks */

#define EPSV     0.05f
#define INV_EPS  20.0f
#define CLOGN    0.45054567f   /* eps * log(8192) */

// ---- scratch (static device memory; allocation-free) ----
__device__ __nv_bfloat16 g_Kxy[NMAT];
__device__ __nv_bfloat16 g_Kyx[NMAT];
__device__ __nv_bfloat16 g_Kxx[NPAIRS * TILE_ELEMS];  // packed lower-triangle tiles
__device__ __nv_bfloat16 g_Kyy[NPAIRS * TILE_ELEMS];

__device__ float g_Prow[2][NPTS][NT];      // row partials [xx|yy][row][Bslot]
__device__ float g_Pcol[4][2][NPTS][NT];   // col partials [quarter][xx|yy][col][Aslot]
__device__ float g_Pxy[2][NPTS][2];        // xy partials [f|g][row][colhalf]

__device__ float g_f[NPTS], g_g[NPTS], g_wf[NPTS], g_wg[NPTS];
__device__ float g_hx[2][NPTS], g_whx[2][NPTS];
__device__ float g_hy[2][NPTS], g_why[2][NPTS];
__device__ float g_cham[NPTS];

__device__ __forceinline__ float bf_lo(unsigned u){ return __uint_as_float(u << 16); }
__device__ __forceinline__ float bf_hi(unsigned u){ return __uint_as_float(u & 0xffff0000u); }

__device__ __forceinline__ void decode_pair(int p, int& A, int& B){
  int a = (int)((sqrtf(8.f * p + 1.f) - 1.f) * 0.5f);
  while ((a + 1) * (a + 2) / 2 <= p) a++;
  while (a * (a + 1) / 2 > p) a--;
  A = a; B = p - ((a * (a + 1)) >> 1);
}

__global__ void init_kernel(){
  int i = blockIdx.x * blockDim.x + threadIdx.x;
  if (i < NPTS){
    g_wf[i] = 1.f; g_wg[i] = 1.f;
    g_whx[0][i] = 1.f; g_whx[1][i] = 1.f;
    g_why[0][i] = 1.f; g_why[1][i] = 1.f;
    g_f[i] = 0.f; g_g[i] = 0.f;
    g_hx[0][i] = 0.f; g_hx[1][i] = 0.f;
    g_hy[0][i] = 0.f; g_hy[1][i] = 0.f;
  }
  int nrow = 2 * NPTS * NT;
  for (int j = i; j < nrow; j += gridDim.x * blockDim.x)
    (&g_Prow[0][0][0])[j] = 0.f;
  int ncol = 4 * 2 * NPTS * NT;
  for (int j = i; j < ncol; j += gridDim.x * blockDim.x)
    (&g_Pcol[0][0][0][0])[j] = 0.f;
}

// xy fills: one block per row. which: 0=Kxy  1=Kyx (+chamfer row mins)
__global__ void __launch_bounds__(256) fill_kernel(const float* __restrict__ Apts,
                                                   const float* __restrict__ Bpts,
                                                   int which){
  __nv_bfloat16* K = (which == 0) ? g_Kxy : g_Kyx;
  float* rowmin = (which == 1) ? g_cham : nullptr;

  int row = blockIdx.x;
  float4 ap = reinterpret_cast<const float4*>(Apts)[row];
  float na = ap.x*ap.x + ap.y*ap.y + ap.z*ap.z;
  float mn = INFINITY;
  unsigned* Kout = reinterpret_cast<unsigned*>(K + ((size_t)row << 13));
  const float4* Bv = reinterpret_cast<const float4*>(Bpts);

  for (int k = threadIdx.x; k < NPTS/2; k += 256){
    float4 b0 = Bv[2*k], b1 = Bv[2*k + 1];
    float d0 = fmaxf(na + (b0.x*b0.x + b0.y*b0.y + b0.z*b0.z)
                        - 2.f*(ap.x*b0.x + ap.y*b0.y + ap.z*b0.z), 0.f);
    float d1 = fmaxf(na + (b1.x*b1.x + b1.y*b1.y + b1.z*b1.z)
                        - 2.f*(ap.x*b1.x + ap.y*b1.y + ap.z*b1.z), 0.f);
    mn = fminf(mn, fminf(d0, d1));
    float e0 = __expf(-INV_EPS * sqrtf(d0 + 1e-12f));
    float e1 = __expf(-INV_EPS * sqrtf(d1 + 1e-12f));
    __nv_bfloat162 p = __floats2bfloat162_rn(e0, e1);
    Kout[k] = *reinterpret_cast<unsigned*>(&p);
  }

  if (rowmin){
    __shared__ float sredm[8];
    int lane = threadIdx.x & 31, wid = threadIdx.x >> 5;
    #pragma unroll
    for (int o = 16; o; o >>= 1) mn = fminf(mn, __shfl_xor_sync(0xffffffffu, mn, o));
    if (lane == 0) sredm[wid] = mn;
    __syncthreads();
    if (threadIdx.x == 0){
      float m = sredm[0];
      #pragma unroll
      for (int w = 1; w < 8; w++) m = fminf(m, sredm[w]);
      rowmin[row] = m;
    }
  }
}

// Packed symmetric fills: 8 tile-rows per block.
__global__ void __launch_bounds__(256) fill_sym_kernel(const float* __restrict__ xpts,
                                                       const float* __restrict__ ypts){
  __shared__ __align__(16) float4 sB[TS];
  int blk = blockIdx.x;
  int mat = (blk >= NPAIRS * 64) ? 1 : 0;
  if (mat) blk -= NPAIRS * 64;
  int p  = blk >> 6;
  int rr = (blk & 63) << 3;
  int A, B; decode_pair(p, A, B);

  const float* pts = mat ? ypts : xpts;
  __nv_bfloat16* out = (mat ? g_Kyy : g_Kxx) + (size_t)p * TILE_ELEMS;

  const float4* P4 = reinterpret_cast<const float4*>(pts);
  for (int i = threadIdx.x; i < TS; i += 256) sB[i] = P4[B * TS + i];
  __syncthreads();

  int lane = threadIdx.x & 31, wid = threadIdx.x >> 5;
  int r = rr + wid;
  float4 ap = P4[A * TS + r];
  float na = ap.x*ap.x + ap.y*ap.y + ap.z*ap.z;
  unsigned* orow = reinterpret_cast<unsigned*>(out + ((size_t)r << 9));

  #pragma unroll
  for (int c0 = 0; c0 < 8; c0++){
    int c = (c0 << 5) + lane;
    float4 b0 = sB[2*c], b1 = sB[2*c + 1];
    float d0 = fmaxf(na + (b0.x*b0.x + b0.y*b0.y + b0.z*b0.z)
                        - 2.f*(ap.x*b0.x + ap.y*b0.y + ap.z*b0.z), 0.f);
    float d1 = fmaxf(na + (b1.x*b1.x + b1.y*b1.y + b1.z*b1.z)
                        - 2.f*(ap.x*b1.x + ap.y*b1.y + ap.z*b1.z), 0.f);
    float e0 = __expf(-INV_EPS * sqrtf(d0 + 1e-12f));
    float e1 = __expf(-INV_EPS * sqrtf(d1 + 1e-12f));
    __nv_bfloat162 pk = __floats2bfloat162_rn(e0, e1);
    orow[c] = *reinterpret_cast<unsigned*>(&pk);
  }
}

// ---- finish device functions ----
// sym finish for step tf: 64 blocks' worth (blk 0..63), 16384 threads total.
__device__ __forceinline__ void sym_finish(int tf, int blk, int tid){
  int idx = blk * 256 + tid;      // 0..16383
  int mat = idx >> 13;
  int r   = idx & (NPTS - 1);
  const float4* Pr = reinterpret_cast<const float4*>(g_Prow[mat][r]);
  float4 a0 = Pr[0], a1 = Pr[1], a2 = Pr[2], a3 = Pr[3];
  float s = (a0.x+a0.y+a0.z+a0.w) + (a1.x+a1.y+a1.z+a1.w)
          + (a2.x+a2.y+a2.z+a2.w) + (a3.x+a3.y+a3.z+a3.w);
  #pragma unroll
  for (int qq = 0; qq < 4; qq++){
    const float4* Pc = reinterpret_cast<const float4*>(g_Pcol[qq][mat][r]);
    float4 c0 = Pc[0], c1 = Pc[1], c2 = Pc[2], c3 = Pc[3];
    s += (c0.x+c0.y+c0.z+c0.w) + (c1.x+c1.y+c1.z+c1.w)
       + (c2.x+c2.y+c2.z+c2.w) + (c3.x+c3.y+c3.z+c3.w);
  }
  s = fmaxf(s, 1e-35f);
  float val = CLOGN - EPSV * __logf(s);
  int out = tf & 1;
  if (mat == 0){ g_hx[out][r] = val; g_whx[out][r] = 8192.f / s; }
  else         { g_hy[out][r] = val; g_why[out][r] = 8192.f / s; }
}

// xy finish for step t: 32 blocks' worth (blk 0..31), 8192 threads total.
__device__ __forceinline__ void xy_finish(int t, int blk, int tid){
  int r = blk * 256 + tid;        // 0..8191
  int side = t & 1;               // 0: f just written, 1: g
  float2 pp = *reinterpret_cast<const float2*>(g_Pxy[side][r]);
  float s = fmaxf(pp.x + pp.y, 1e-35f);
  float val = CLOGN - EPSV * __logf(s);
  if (side == 0){ g_f[r] = val; g_wf[r] = 8192.f / s; }
  else          { g_g[r] = val; g_wg[r] = 8192.f / s; }
}

// K1(t): blocks 0..1023 = xy step(t); blocks 1024..1087 = sym finish(t-1).
__global__ void __launch_bounds__(256) step1_kernel(int t){
  __shared__ __align__(16) float sbuf[4096];
  int tid = threadIdx.x, lane = tid & 31, wid = tid >> 5;
  int b = blockIdx.x;
  bool even = (t & 1) == 0;

  if (b >= 1024){
    if (t > 0) sym_finish(t - 1, b - 1024, tid);
    return;
  }

  // ---------------- xy chain: 16 rows x 4096 cols ----------------
  const __nv_bfloat16* K = even ? g_Kxy : g_Kyx;
  const float* win  = even ? g_wg : g_wf;
  float (*Pout)[2]  = even ? g_Pxy[0] : g_Pxy[1];
  int rowgrp = b >> 1, half = b & 1;
  int cbase = half << 12;

  float* sw = sbuf;   // 4096 w values for this column half
  for (int i = tid; i < 1024; i += 256)
    reinterpret_cast<float4*>(sw)[i] = reinterpret_cast<const float4*>(win + cbase)[i];
  __syncthreads();

  int row0 = (rowgrp << 4) + (wid << 1);
  const uint4* K0 = reinterpret_cast<const uint4*>(K + ((size_t)row0 << 13) + cbase);
  const uint4* K1 = reinterpret_cast<const uint4*>(K + ((size_t)(row0 + 1) << 13) + cbase);
  float s0 = 0.f, s1 = 0.f;
  #pragma unroll 4
  for (int it = lane; it < 512; it += 32){
    uint4 a = K0[it];
    uint4 c = K1[it];
    const float4* vp = reinterpret_cast<const float4*>(sw + (it << 3));
    float4 v0 = vp[0], v1 = vp[1];
    s0 += bf_lo(a.x)*v0.x + bf_hi(a.x)*v0.y + bf_lo(a.y)*v0.z + bf_hi(a.y)*v0.w
        + bf_lo(a.z)*v1.x + bf_hi(a.z)*v1.y + bf_lo(a.w)*v1.z + bf_hi(a.w)*v1.w;
    s1 += bf_lo(c.x)*v0.x + bf_hi(c.x)*v0.y + bf_lo(c.y)*v0.z + bf_hi(c.y)*v0.w
        + bf_lo(c.z)*v1.x + bf_hi(c.z)*v1.y + bf_lo(c.w)*v1.z + bf_hi(c.w)*v1.w;
  }
  #pragma unroll
  for (int o = 16; o; o >>= 1){
    s0 += __shfl_xor_sync(0xffffffffu, s0, o);
    s1 += __shfl_xor_sync(0xffffffffu, s1, o);
  }
  if (lane == 0){
    Pout[row0][half]     = s0;
    Pout[row0 + 1][half] = s1;
  }
}

// K2(t): blocks 0..NSYMB-1 = sym quarter-tile step(t); blocks NSYMB.. = xy finish(t).
__global__ void __launch_bounds__(256) step2_kernel(int t){
  __shared__ __align__(16) float sbuf[4736];
  int tid = threadIdx.x, lane = tid & 31, wid = tid >> 5;
  int b = blockIdx.x;

  if (b >= NSYMB){
    xy_finish(t, b - NSYMB, tid);
    return;
  }

  // ------------- symmetric chains: quarter-tiles -------------
  int mat = (b >= NPAIRS * 4) ? 1 : 0;
  int q   = mat ? b - NPAIRS * 4 : b;
  int p   = q >> 2, quarter = q & 3;
  int A, B; decode_pair(p, A, B);
  bool diag = (A == B);

  const __nv_bfloat16* Ktile = (mat ? g_Kyy : g_Kxx)
                             + (size_t)p * TILE_ELEMS + ((size_t)(quarter * QR) << 9);
  int in = ((t & 1) ^ 1);
  const float* win = mat ? g_why[in] : g_whx[in];

  float* wcol = sbuf;             // 512 (columns = B block)
  float* wrow = sbuf + TS;        // 128 (this quarter's rows)
  float* cs   = sbuf + TS + QR;   // 8 * 512 staging

  for (int i = tid; i < TS; i += 256) wcol[i] = win[B * TS + i];
  if (tid < QR) wrow[tid] = win[A * TS + quarter * QR + tid];
  __syncthreads();

  float4 acc[4];
  #pragma unroll
  for (int i = 0; i < 4; i++) acc[i] = make_float4(0.f, 0.f, 0.f, 0.f);

  for (int r = wid; r < QR; r += 8){
    const uint4* Kr = reinterpret_cast<const uint4*>(Ktile + ((size_t)r << 9));
    float wr = wrow[r];
    float rd = 0.f;
    #pragma unroll
    for (int i = 0; i < 2; i++){
      uint4 kk = Kr[(i << 5) + lane];
      const float4* wp = reinterpret_cast<const float4*>(wcol + (i << 8) + (lane << 3));
      float4 w0 = wp[0], w1 = wp[1];
      float k0 = bf_lo(kk.x), k1 = bf_hi(kk.x), k2 = bf_lo(kk.y), k3 = bf_hi(kk.y);
      float k4 = bf_lo(kk.z), k5 = bf_hi(kk.z), k6 = bf_lo(kk.w), k7 = bf_hi(kk.w);
      rd += k0*w0.x + k1*w0.y + k2*w0.z + k3*w0.w
          + k4*w1.x + k5*w1.y + k6*w1.z + k7*w1.w;
      if (!diag){
        acc[2*i].x   += k0 * wr;  acc[2*i].y   += k1 * wr;
        acc[2*i].z   += k2 * wr;  acc[2*i].w   += k3 * wr;
        acc[2*i+1].x += k4 * wr;  acc[2*i+1].y += k5 * wr;
        acc[2*i+1].z += k6 * wr;  acc[2*i+1].w += k7 * wr;
      }
    }
    #pragma unroll
    for (int o = 16; o; o >>= 1) rd += __shfl_xor_sync(0xffffffffu, rd, o);
    if (lane == 0)
      g_Prow[mat][A * TS + quarter * QR + r][B] = rd;
  }

  if (!diag){
    #pragma unroll
    for (int i = 0; i < 2; i++){
      *reinterpret_cast<float4*>(cs + wid * TS + (i << 8) + (lane << 3))     = acc[2*i];
      *reinterpret_cast<float4*>(cs + wid * TS + (i << 8) + (lane << 3) + 4) = acc[2*i+1];
    }
    __syncthreads();
    for (int c = tid; c < TS; c += 256){
      float s = 0.f;
      #pragma unroll
      for (int w = 0; w < 8; w++) s += cs[w * TS + c];
      g_Pcol[quarter][mat][B * TS + c][A] = s;
    }
  }
}

// Standalone sym finish for the last step (t = 99).
__global__ void __launch_bounds__(256) symfin_kernel(int tf){
  sym_finish(tf, blockIdx.x, threadIdx.x);
}

__global__ void final_kernel(float* out){
  __shared__ float sred[8];
  int tid = threadIdx.x, lane = tid & 31, wid = tid >> 5;
  const float* arrs[7] = { g_f, g_g, g_hx[0], g_hx[1], g_hy[0], g_hy[1], g_cham };
  float totals[7];
  for (int a = 0; a < 7; a++){
    float s = 0.f;
    for (int i = tid; i < NPTS; i += 256) s += arrs[a][i];
    #pragma unroll
    for (int o = 16; o; o >>= 1) s += __shfl_xor_sync(0xffffffffu, s, o);
    __syncthreads();
    if (lane == 0) sred[wid] = s;
    __syncthreads();
    if (tid == 0){
      float tt = 0.f;
      #pragma unroll
      for (int w = 0; w < 8; w++) tt += sred[w];
      totals[a] = tt;
    }
  }
  if (tid == 0){
    const float invN = 1.f / (float)NPTS;
    float ot_xy = (totals[0] + totals[1]) * invN;
    float ot_xx = (totals[2] + totals[3]) * invN;
    float ot_yy = (totals[4] + totals[5]) * invN;
    float cham  = totals[6] * invN;
    float emd = ot_xy - 0.5f * ot_xx - 0.5f * ot_yy;
    out[0] = 0.2f * cham + 0.8f * emd;
  }
}

extern "C" void kernel_launch(void* const* d_in, const int* in_sizes, int n_in,
                              void* d_out, int out_size){
  const float* pred = (const float*)d_in[0];
  const float* gt   = (const float*)d_in[1];
  float* out = (float*)d_out;

  init_kernel<<<256, 256>>>();
  fill_kernel<<<NPTS, 256>>>(pred, gt,   0);            // Kxy
  fill_kernel<<<NPTS, 256>>>(gt,   pred, 1);            // Kyx + chamfer row mins
  fill_sym_kernel<<<2 * NPAIRS * 64, 256>>>(pred, gt);  // packed Kxx + Kyy

  for (int t = 0; t < 100; t++){
    step1_kernel<<<1024 + 64, 256>>>(t);     // xy step(t) + sym finish(t-1)
    step2_kernel<<<NSYMB + 32, 256>>>(t);    // sym step(t) + xy finish(t)
  }

  symfin_kernel<<<64, 256>>>(99);            // sym finish of last step
  final_kernel<<<1, 256>>>(out);
}

// round 14
// speedup vs baseline: 1.5338x; 1.2310x over previous
#include <cuda_runtime.h>
#include <cuda_bf16.h>
#include <cstdint>
#include <math.h>

#define NPTS 8192
#define NMAT ((size_t)NPTS * (size_t)NPTS)
#define TS   512
#define HR   256                        /* rows per half-tile block */
#define NT   16
#define NPAIRS 136                      /* NT*(NT+1)/2 */
#define TILE_ELEMS ((size_t)TS * TS)
#define NSYMB (2 * NPAIRS * 2)          /* 544 sym half-tile blocks */

#define EPSV     0.05f
#define INV_EPS  20.0f
#define CLOGN    0.45054567f   /* eps * log(8192) */

// ---- scratch (static device memory; allocation-free) ----
__device__ __nv_bfloat16 g_Kxy[NMAT];
__device__ __nv_bfloat16 g_Kyx[NMAT];
__device__ __nv_bfloat16 g_Kxx[NPAIRS * TILE_ELEMS];  // packed lower-triangle tiles
__device__ __nv_bfloat16 g_Kyy[NPAIRS * TILE_ELEMS];

__device__ float g_P[2][2][NPTS][NT];   // sym partials [half][xx|yy][row][slot]
__device__ float g_Pxy[2][NPTS][2];     // xy partials [f|g][row][colhalf]

__device__ float g_f[NPTS], g_g[NPTS], g_wf[NPTS], g_wg[NPTS];
__device__ float g_hx[2][NPTS], g_whx[2][NPTS];
__device__ float g_hy[2][NPTS], g_why[2][NPTS];
__device__ float g_cham[NPTS];

__device__ __forceinline__ float bf_lo(unsigned u){ return __uint_as_float(u << 16); }
__device__ __forceinline__ float bf_hi(unsigned u){ return __uint_as_float(u & 0xffff0000u); }

__device__ __forceinline__ void decode_pair(int p, int& A, int& B){
  int a = (int)((sqrtf(8.f * p + 1.f) - 1.f) * 0.5f);
  while ((a + 1) * (a + 2) / 2 <= p) a++;
  while (a * (a + 1) / 2 > p) a--;
  A = a; B = p - ((a * (a + 1)) >> 1);
}

__global__ void init_kernel(){
  int i = blockIdx.x * blockDim.x + threadIdx.x;
  if (i < NPTS){
    g_wf[i] = 1.f; g_wg[i] = 1.f;
    g_whx[0][i] = 1.f; g_whx[1][i] = 1.f;
    g_why[0][i] = 1.f; g_why[1][i] = 1.f;
    g_f[i] = 0.f; g_g[i] = 0.f;
    g_hx[0][i] = 0.f; g_hx[1][i] = 0.f;
    g_hy[0][i] = 0.f; g_hy[1][i] = 0.f;
  }
  // zero sym partials once: slots never written by any step stay 0 forever
  int tot = 2 * 2 * NPTS * NT;
  for (int j = i; j < tot; j += gridDim.x * blockDim.x)
    (&g_P[0][0][0][0])[j] = 0.f;
}

// xy fills: one block per row. which: 0=Kxy  1=Kyx (+chamfer row mins)
__global__ void __launch_bounds__(256) fill_kernel(const float* __restrict__ Apts,
                                                   const float* __restrict__ Bpts,
                                                   int which){
  __nv_bfloat16* K = (which == 0) ? g_Kxy : g_Kyx;
  float* rowmin = (which == 1) ? g_cham : nullptr;

  int row = blockIdx.x;
  float4 ap = reinterpret_cast<const float4*>(Apts)[row];
  float na = ap.x*ap.x + ap.y*ap.y + ap.z*ap.z;
  float mn = INFINITY;
  unsigned* Kout = reinterpret_cast<unsigned*>(K + ((size_t)row << 13));
  const float4* Bv = reinterpret_cast<const float4*>(Bpts);

  for (int k = threadIdx.x; k < NPTS/2; k += 256){
    float4 b0 = Bv[2*k], b1 = Bv[2*k + 1];
    float d0 = fmaxf(na + (b0.x*b0.x + b0.y*b0.y + b0.z*b0.z)
                        - 2.f*(ap.x*b0.x + ap.y*b0.y + ap.z*b0.z), 0.f);
    float d1 = fmaxf(na + (b1.x*b1.x + b1.y*b1.y + b1.z*b1.z)
                        - 2.f*(ap.x*b1.x + ap.y*b1.y + ap.z*b1.z), 0.f);
    mn = fminf(mn, fminf(d0, d1));
    float e0 = __expf(-INV_EPS * sqrtf(d0 + 1e-12f));
    float e1 = __expf(-INV_EPS * sqrtf(d1 + 1e-12f));
    __nv_bfloat162 p = __floats2bfloat162_rn(e0, e1);
    Kout[k] = *reinterpret_cast<unsigned*>(&p);
  }

  if (rowmin){
    __shared__ float sredm[8];
    int lane = threadIdx.x & 31, wid = threadIdx.x >> 5;
    #pragma unroll
    for (int o = 16; o; o >>= 1) mn = fminf(mn, __shfl_xor_sync(0xffffffffu, mn, o));
    if (lane == 0) sredm[wid] = mn;
    __syncthreads();
    if (threadIdx.x == 0){
      float m = sredm[0];
      #pragma unroll
      for (int w = 1; w < 8; w++) m = fminf(m, sredm[w]);
      rowmin[row] = m;
    }
  }
}

// Packed symmetric fills: 8 tile-rows per block.
__global__ void __launch_bounds__(256) fill_sym_kernel(const float* __restrict__ xpts,
                                                       const float* __restrict__ ypts){
  __shared__ __align__(16) float4 sB[TS];
  int blk = blockIdx.x;
  int mat = (blk >= NPAIRS * 64) ? 1 : 0;
  if (mat) blk -= NPAIRS * 64;
  int p  = blk >> 6;
  int rr = (blk & 63) << 3;
  int A, B; decode_pair(p, A, B);

  const float* pts = mat ? ypts : xpts;
  __nv_bfloat16* out = (mat ? g_Kyy : g_Kxx) + (size_t)p * TILE_ELEMS;

  const float4* P4 = reinterpret_cast<const float4*>(pts);
  for (int i = threadIdx.x; i < TS; i += 256) sB[i] = P4[B * TS + i];
  __syncthreads();

  int lane = threadIdx.x & 31, wid = threadIdx.x >> 5;
  int r = rr + wid;
  float4 ap = P4[A * TS + r];
  float na = ap.x*ap.x + ap.y*ap.y + ap.z*ap.z;
  unsigned* orow = reinterpret_cast<unsigned*>(out + ((size_t)r << 9));

  #pragma unroll
  for (int c0 = 0; c0 < 8; c0++){
    int c = (c0 << 5) + lane;
    float4 b0 = sB[2*c], b1 = sB[2*c + 1];
    float d0 = fmaxf(na + (b0.x*b0.x + b0.y*b0.y + b0.z*b0.z)
                        - 2.f*(ap.x*b0.x + ap.y*b0.y + ap.z*b0.z), 0.f);
    float d1 = fmaxf(na + (b1.x*b1.x + b1.y*b1.y + b1.z*b1.z)
                        - 2.f*(ap.x*b1.x + ap.y*b1.y + ap.z*b1.z), 0.f);
    float e0 = __expf(-INV_EPS * sqrtf(d0 + 1e-12f));
    float e1 = __expf(-INV_EPS * sqrtf(d1 + 1e-12f));
    __nv_bfloat162 pk = __floats2bfloat162_rn(e0, e1);
    orow[c] = *reinterpret_cast<unsigned*>(&pk);
  }
}

// Blocks 0..543: symmetric half-tiles (256KB work, dispatched FIRST).
// Blocks 544..1567: xy chain, 16 rows x 4096 cols (128KB work, fine-grained tail).
__global__ void __launch_bounds__(256) step_kernel(int t){
  __shared__ __align__(16) float sbuf[5120];
  int tid = threadIdx.x, lane = tid & 31, wid = tid >> 5;
  int b = blockIdx.x;
  bool even = (t & 1) == 0;

  if (b < NSYMB){
    // ------------- symmetric chains: half-tiles -------------
    int mat = (b >= 2 * NPAIRS) ? 1 : 0;
    int q   = mat ? b - 2 * NPAIRS : b;
    int p   = q >> 1, half = q & 1;
    int A, B; decode_pair(p, A, B);
    bool diag = (A == B);

    const __nv_bfloat16* Ktile = (mat ? g_Kyy : g_Kxx)
                               + (size_t)p * TILE_ELEMS + ((size_t)half * HR << 9);
    int in = ((t & 1) ^ 1);
    const float* win = mat ? g_why[in] : g_whx[in];

    float* wcol = sbuf;            // 512 (columns = B block)
    float* wrow = sbuf + TS;       // 256 (this half's rows)
    float* cs   = sbuf + TS + HR;  // 8 * 512 staging

    for (int i = tid; i < TS; i += 256) wcol[i] = win[B * TS + i];
    for (int i = tid; i < HR; i += 256) wrow[i] = win[A * TS + half * HR + i];
    __syncthreads();

    float4 acc[4];
    #pragma unroll
    for (int i = 0; i < 4; i++) acc[i] = make_float4(0.f, 0.f, 0.f, 0.f);

    for (int r = wid; r < HR; r += 8){
      const uint4* Kr = reinterpret_cast<const uint4*>(Ktile + ((size_t)r << 9));
      float wr = wrow[r];
      float rd = 0.f;
      #pragma unroll
      for (int i = 0; i < 2; i++){
        uint4 kk = Kr[(i << 5) + lane];
        const float4* wp = reinterpret_cast<const float4*>(wcol + (i << 8) + (lane << 3));
        float4 w0 = wp[0], w1 = wp[1];
        float k0 = bf_lo(kk.x), k1 = bf_hi(kk.x), k2 = bf_lo(kk.y), k3 = bf_hi(kk.y);
        float k4 = bf_lo(kk.z), k5 = bf_hi(kk.z), k6 = bf_lo(kk.w), k7 = bf_hi(kk.w);
        rd += k0*w0.x + k1*w0.y + k2*w0.z + k3*w0.w
            + k4*w1.x + k5*w1.y + k6*w1.z + k7*w1.w;
        if (!diag){
          acc[2*i].x   += k0 * wr;  acc[2*i].y   += k1 * wr;
          acc[2*i].z   += k2 * wr;  acc[2*i].w   += k3 * wr;
          acc[2*i+1].x += k4 * wr;  acc[2*i+1].y += k5 * wr;
          acc[2*i+1].z += k6 * wr;  acc[2*i+1].w += k7 * wr;
        }
      }
      #pragma unroll
      for (int o = 16; o; o >>= 1) rd += __shfl_xor_sync(0xffffffffu, rd, o);
      if (lane == 0)
        g_P[0][mat][A * TS + half * HR + r][B] = rd;
    }

    if (!diag){
      #pragma unroll
      for (int i = 0; i < 2; i++){
        *reinterpret_cast<float4*>(cs + wid * TS + (i << 8) + (lane << 3))     = acc[2*i];
        *reinterpret_cast<float4*>(cs + wid * TS + (i << 8) + (lane << 3) + 4) = acc[2*i+1];
      }
      __syncthreads();
      for (int c = tid; c < TS; c += 256){
        float s = 0.f;
        #pragma unroll
        for (int w = 0; w < 8; w++) s += cs[w * TS + c];
        g_P[half][mat][B * TS + c][A] = s;
      }
    }
  } else {
    // ---------------- xy chain: half-row matvec, partial output ----------------
    int b2 = b - NSYMB;
    const __nv_bfloat16* K = even ? g_Kxy : g_Kyx;
    const float* win  = even ? g_wg : g_wf;
    float (*Pout)[2]  = even ? g_Pxy[0] : g_Pxy[1];
    int rowgrp = b2 >> 1, half = b2 & 1;
    int cbase = half << 12;

    float* sw = sbuf;   // 4096 w values for this column half
    for (int i = tid; i < 1024; i += 256)
      reinterpret_cast<float4*>(sw)[i] = reinterpret_cast<const float4*>(win + cbase)[i];
    __syncthreads();

    int row0 = (rowgrp << 4) + (wid << 1);
    const uint4* K0 = reinterpret_cast<const uint4*>(K + ((size_t)row0 << 13) + cbase);
    const uint4* K1 = reinterpret_cast<const uint4*>(K + ((size_t)(row0 + 1) << 13) + cbase);
    float s0 = 0.f, s1 = 0.f;
    #pragma unroll 4
    for (int it = lane; it < 512; it += 32){
      uint4 a = K0[it];
      uint4 c = K1[it];
      const float4* vp = reinterpret_cast<const float4*>(sw + (it << 3));
      float4 v0 = vp[0], v1 = vp[1];
      s0 += bf_lo(a.x)*v0.x + bf_hi(a.x)*v0.y + bf_lo(a.y)*v0.z + bf_hi(a.y)*v0.w
          + bf_lo(a.z)*v1.x + bf_hi(a.z)*v1.y + bf_lo(a.w)*v1.z + bf_hi(a.w)*v1.w;
      s1 += bf_lo(c.x)*v0.x + bf_hi(c.x)*v0.y + bf_lo(c.y)*v0.z + bf_hi(c.y)*v0.w
          + bf_lo(c.z)*v1.x + bf_hi(c.z)*v1.y + bf_lo(c.w)*v1.z + bf_hi(c.w)*v1.w;
    }
    #pragma unroll
    for (int o = 16; o; o >>= 1){
      s0 += __shfl_xor_sync(0xffffffffu, s0, o);
      s1 += __shfl_xor_sync(0xffffffffu, s1, o);
    }
    if (lane == 0){
      Pout[row0][half]     = s0;
      Pout[row0 + 1][half] = s1;
    }
  }
}

// Per-step reduce: xy partials (side of this step) + sym partials (both chains).
__global__ void __launch_bounds__(256) finish_kernel(int t){
  int idx = blockIdx.x * 256 + threadIdx.x;   // 0..24575
  int a = idx >> 13;                          // 0=xy, 1=hx, 2=hy
  int r = idx & (NPTS - 1);
  if (a == 0){
    int side = t & 1;                         // 0: f just written, 1: g
    float2 pp = *reinterpret_cast<const float2*>(g_Pxy[side][r]);
    float s = fmaxf(pp.x + pp.y, 1e-35f);
    float val = CLOGN - EPSV * __logf(s);
    if (side == 0){ g_f[r] = val; g_wf[r] = 8192.f / s; }
    else          { g_g[r] = val; g_wg[r] = 8192.f / s; }
  } else {
    int mat = a - 1;
    const float4* P0 = reinterpret_cast<const float4*>(&g_P[0][mat][r][0]);
    const float4* P1 = reinterpret_cast<const float4*>(&g_P[1][mat][r][0]);
    float4 a0 = P0[0], a1 = P0[1], a2 = P0[2], a3 = P0[3];
    float4 b0 = P1[0], b1 = P1[1], b2 = P1[2], b3 = P1[3];
    float s = (a0.x+a0.y+a0.z+a0.w) + (a1.x+a1.y+a1.z+a1.w)
            + (a2.x+a2.y+a2.z+a2.w) + (a3.x+a3.y+a3.z+a3.w)
            + (b0.x+b0.y+b0.z+b0.w) + (b1.x+b1.y+b1.z+b1.w)
            + (b2.x+b2.y+b2.z+b2.w) + (b3.x+b3.y+b3.z+b3.w);
    s = fmaxf(s, 1e-35f);
    float val = CLOGN - EPSV * __logf(s);
    int out = t & 1;
    if (mat == 0){ g_hx[out][r] = val; g_whx[out][r] = 8192.f / s; }
    else         { g_hy[out][r] = val; g_why[out][r] = 8192.f / s; }
  }
}

__global__ void final_kernel(float* out){
  __shared__ float sred[8];
  int tid = threadIdx.x, lane = tid & 31, wid = tid >> 5;
  const float* arrs[7] = { g_f, g_g, g_hx[0], g_hx[1], g_hy[0], g_hy[1], g_cham };
  float totals[7];
  for (int a = 0; a < 7; a++){
    float s = 0.f;
    for (int i = tid; i < NPTS; i += 256) s += arrs[a][i];
    #pragma unroll
    for (int o = 16; o; o >>= 1) s += __shfl_xor_sync(0xffffffffu, s, o);
    __syncthreads();
    if (lane == 0) sred[wid] = s;
    __syncthreads();
    if (tid == 0){
      float tt = 0.f;
      #pragma unroll
      for (int w = 0; w < 8; w++) tt += sred[w];
      totals[a] = tt;
    }
  }
  if (tid == 0){
    const float invN = 1.f / (float)NPTS;
    float ot_xy = (totals[0] + totals[1]) * invN;
    float ot_xx = (totals[2] + totals[3]) * invN;
    float ot_yy = (totals[4] + totals[5]) * invN;
    float cham  = totals[6] * invN;
    float emd = ot_xy - 0.5f * ot_xx - 0.5f * ot_yy;
    out[0] = 0.2f * cham + 0.8f * emd;
  }
}

extern "C" void kernel_launch(void* const* d_in, const int* in_sizes, int n_in,
                              void* d_out, int out_size){
  const float* pred = (const float*)d_in[0];
  const float* gt   = (const float*)d_in[1];
  float* out = (float*)d_out;

  init_kernel<<<256, 256>>>();
  fill_kernel<<<NPTS, 256>>>(pred, gt,   0);            // Kxy
  fill_kernel<<<NPTS, 256>>>(gt,   pred, 1);            // Kyx + chamfer row mins
  fill_sym_kernel<<<2 * NPAIRS * 64, 256>>>(pred, gt);  // packed Kxx + Kyy

  for (int t = 0; t < 100; t++){
    step_kernel<<<NSYMB + 1024, 256>>>(t);
    finish_kernel<<<96, 256>>>(t);
  }

  final_kernel<<<1, 256>>>(out);
}

// round 15
// speedup vs baseline: 1.5340x; 1.0002x over previous
#include <cuda_runtime.h>
#include <cuda_bf16.h>
#include <cstdint>
#include <math.h>

#define NPTS 8192
#define NMAT ((size_t)NPTS * (size_t)NPTS)
#define TS   512
#define HR   256                        /* rows per half-tile block */
#define NT   16
#define NPAIRS 136                      /* NT*(NT+1)/2 */
#define TILE_ELEMS ((size_t)TS * TS)
#define NSYMB (2 * NPAIRS * 2)          /* 544 sym half-tile blocks */

#define EPSV     0.05f
#define INV_EPS  20.0f
#define CLOGN    0.45054567f   /* eps * log(8192) */

// ---- scratch (static device memory; allocation-free) ----
__device__ __nv_bfloat16 g_Kxy[NMAT];
__device__ __nv_bfloat16 g_Kyx[NMAT];
__device__ __nv_bfloat16 g_Kxx[NPAIRS * TILE_ELEMS];  // packed lower-triangle tiles
__device__ __nv_bfloat16 g_Kyy[NPAIRS * TILE_ELEMS];

__device__ float g_P[2][2][NPTS][NT];   // sym partials [half][xx|yy][row][slot]
__device__ float g_Pxy[2][NPTS][2];     // xy partials [f|g][row][colhalf]

__device__ float g_f[NPTS], g_g[NPTS], g_wf[NPTS], g_wg[NPTS];
__device__ float g_hx[2][NPTS], g_whx[2][NPTS];
__device__ float g_hy[2][NPTS], g_why[2][NPTS];
__device__ float g_cham[NPTS];

__device__ __forceinline__ float bf_lo(unsigned u){ return __uint_as_float(u << 16); }
__device__ __forceinline__ float bf_hi(unsigned u){ return __uint_as_float(u & 0xffff0000u); }

__device__ __forceinline__ void decode_pair(int p, int& A, int& B){
  int a = (int)((sqrtf(8.f * p + 1.f) - 1.f) * 0.5f);
  while ((a + 1) * (a + 2) / 2 <= p) a++;
  while (a * (a + 1) / 2 > p) a--;
  A = a; B = p - ((a * (a + 1)) >> 1);
}

// ---- fused setup kernel ----
// blocks [0, 8192)          : Kxy row fill (rows = pred, cols = gt)
// blocks [8192, 16384)      : Kyx row fill + chamfer row mins (rows = gt, cols = pred)
// blocks [16384, 33792)     : packed sym fills (Kxx then Kyy, 8 tile-rows/block)
// blocks [33792, 34048)     : state init (w arrays, partial zeroing)
__global__ void __launch_bounds__(256) setup_kernel(const float* __restrict__ pred,
                                                    const float* __restrict__ gt){
  __shared__ __align__(16) float4 sB[TS];   // sym path B-point cache (8KB; xy uses tail)
  int b = blockIdx.x;
  int tid = threadIdx.x;

  if (b < 16384){
    // -------- dense xy fills --------
    const float* Apts; const float* Bpts; __nv_bfloat16* K; float* rowmin = nullptr;
    int row;
    if (b < 8192){ Apts = pred; Bpts = gt;   K = g_Kxy; row = b; }
    else         { Apts = gt;   Bpts = pred; K = g_Kyx; row = b - 8192; rowmin = g_cham; }

    float4 ap = reinterpret_cast<const float4*>(Apts)[row];
    float na = ap.x*ap.x + ap.y*ap.y + ap.z*ap.z;
    float mn = INFINITY;
    unsigned* Kout = reinterpret_cast<unsigned*>(K + ((size_t)row << 13));
    const float4* Bv = reinterpret_cast<const float4*>(Bpts);

    for (int k = tid; k < NPTS/2; k += 256){
      float4 b0 = Bv[2*k], b1 = Bv[2*k + 1];
      float d0 = fmaxf(na + (b0.x*b0.x + b0.y*b0.y + b0.z*b0.z)
                          - 2.f*(ap.x*b0.x + ap.y*b0.y + ap.z*b0.z), 0.f);
      float d1 = fmaxf(na + (b1.x*b1.x + b1.y*b1.y + b1.z*b1.z)
                          - 2.f*(ap.x*b1.x + ap.y*b1.y + ap.z*b1.z), 0.f);
      mn = fminf(mn, fminf(d0, d1));
      float e0 = __expf(-INV_EPS * sqrtf(d0 + 1e-12f));
      float e1 = __expf(-INV_EPS * sqrtf(d1 + 1e-12f));
      __nv_bfloat162 p = __floats2bfloat162_rn(e0, e1);
      Kout[k] = *reinterpret_cast<unsigned*>(&p);
    }

    if (rowmin){
      float* sredm = reinterpret_cast<float*>(sB);
      int lane = tid & 31, wid = tid >> 5;
      #pragma unroll
      for (int o = 16; o; o >>= 1) mn = fminf(mn, __shfl_xor_sync(0xffffffffu, mn, o));
      if (lane == 0) sredm[wid] = mn;
      __syncthreads();
      if (tid == 0){
        float m = sredm[0];
        #pragma unroll
        for (int w = 1; w < 8; w++) m = fminf(m, sredm[w]);
        rowmin[row] = m;
      }
    }
  } else if (b < 33792){
    // -------- packed symmetric fills --------
    int blk = b - 16384;
    int mat = (blk >= NPAIRS * 64) ? 1 : 0;
    if (mat) blk -= NPAIRS * 64;
    int p  = blk >> 6;
    int rr = (blk & 63) << 3;
    int A, B; decode_pair(p, A, B);

    const float* pts = mat ? gt : pred;
    __nv_bfloat16* out = (mat ? g_Kyy : g_Kxx) + (size_t)p * TILE_ELEMS;

    const float4* P4 = reinterpret_cast<const float4*>(pts);
    for (int i = tid; i < TS; i += 256) sB[i] = P4[B * TS + i];
    __syncthreads();

    int lane = tid & 31, wid = tid >> 5;
    int r = rr + wid;
    float4 ap = P4[A * TS + r];
    float na = ap.x*ap.x + ap.y*ap.y + ap.z*ap.z;
    unsigned* orow = reinterpret_cast<unsigned*>(out + ((size_t)r << 9));

    #pragma unroll
    for (int c0 = 0; c0 < 8; c0++){
      int c = (c0 << 5) + lane;
      float4 b0 = sB[2*c], b1 = sB[2*c + 1];
      float d0 = fmaxf(na + (b0.x*b0.x + b0.y*b0.y + b0.z*b0.z)
                          - 2.f*(ap.x*b0.x + ap.y*b0.y + ap.z*b0.z), 0.f);
      float d1 = fmaxf(na + (b1.x*b1.x + b1.y*b1.y + b1.z*b1.z)
                          - 2.f*(ap.x*b1.x + ap.y*b1.y + ap.z*b1.z), 0.f);
      float e0 = __expf(-INV_EPS * sqrtf(d0 + 1e-12f));
      float e1 = __expf(-INV_EPS * sqrtf(d1 + 1e-12f));
      __nv_bfloat162 pk = __floats2bfloat162_rn(e0, e1);
      orow[c] = *reinterpret_cast<unsigned*>(&pk);
    }
  } else {
    // -------- state init --------
    int i = (b - 33792) * 256 + tid;
    if (i < NPTS){
      g_wf[i] = 1.f; g_wg[i] = 1.f;
      g_whx[0][i] = 1.f; g_whx[1][i] = 1.f;
      g_why[0][i] = 1.f; g_why[1][i] = 1.f;
      g_f[i] = 0.f; g_g[i] = 0.f;
      g_hx[0][i] = 0.f; g_hx[1][i] = 0.f;
      g_hy[0][i] = 0.f; g_hy[1][i] = 0.f;
    }
    int tot = 2 * 2 * NPTS * NT;
    for (int j = i; j < tot; j += 256 * 256)
      (&g_P[0][0][0][0])[j] = 0.f;
  }
}

// Blocks 0..543: symmetric half-tiles (256KB work, dispatched FIRST).
// Blocks 544..1567: xy chain, 16 rows x 4096 cols (128KB work, fine-grained tail).
__global__ void __launch_bounds__(256) step_kernel(int t){
  __shared__ __align__(16) float sbuf[5120];
  int tid = threadIdx.x, lane = tid & 31, wid = tid >> 5;
  int b = blockIdx.x;
  bool even = (t & 1) == 0;

  if (b < NSYMB){
    // ------------- symmetric chains: half-tiles -------------
    int mat = (b >= 2 * NPAIRS) ? 1 : 0;
    int q   = mat ? b - 2 * NPAIRS : b;
    int p   = q >> 1, half = q & 1;
    int A, B; decode_pair(p, A, B);
    bool diag = (A == B);

    const __nv_bfloat16* Ktile = (mat ? g_Kyy : g_Kxx)
                               + (size_t)p * TILE_ELEMS + ((size_t)half * HR << 9);
    int in = ((t & 1) ^ 1);
    const float* win = mat ? g_why[in] : g_whx[in];

    float* wcol = sbuf;            // 512 (columns = B block)
    float* wrow = sbuf + TS;       // 256 (this half's rows)
    float* cs   = sbuf + TS + HR;  // 8 * 512 staging

    for (int i = tid; i < TS; i += 256) wcol[i] = win[B * TS + i];
    for (int i = tid; i < HR; i += 256) wrow[i] = win[A * TS + half * HR + i];
    __syncthreads();

    float4 acc[4];
    #pragma unroll
    for (int i = 0; i < 4; i++) acc[i] = make_float4(0.f, 0.f, 0.f, 0.f);

    for (int r = wid; r < HR; r += 8){
      const uint4* Kr = reinterpret_cast<const uint4*>(Ktile + ((size_t)r << 9));
      float wr = wrow[r];
      float rd = 0.f;
      #pragma unroll
      for (int i = 0; i < 2; i++){
        uint4 kk = Kr[(i << 5) + lane];
        const float4* wp = reinterpret_cast<const float4*>(wcol + (i << 8) + (lane << 3));
        float4 w0 = wp[0], w1 = wp[1];
        float k0 = bf_lo(kk.x), k1 = bf_hi(kk.x), k2 = bf_lo(kk.y), k3 = bf_hi(kk.y);
        float k4 = bf_lo(kk.z), k5 = bf_hi(kk.z), k6 = bf_lo(kk.w), k7 = bf_hi(kk.w);
        rd += k0*w0.x + k1*w0.y + k2*w0.z + k3*w0.w
            + k4*w1.x + k5*w1.y + k6*w1.z + k7*w1.w;
        if (!diag){
          acc[2*i].x   += k0 * wr;  acc[2*i].y   += k1 * wr;
          acc[2*i].z   += k2 * wr;  acc[2*i].w   += k3 * wr;
          acc[2*i+1].x += k4 * wr;  acc[2*i+1].y += k5 * wr;
          acc[2*i+1].z += k6 * wr;  acc[2*i+1].w += k7 * wr;
        }
      }
      #pragma unroll
      for (int o = 16; o; o >>= 1) rd += __shfl_xor_sync(0xffffffffu, rd, o);
      if (lane == 0)
        g_P[0][mat][A * TS + half * HR + r][B] = rd;
    }

    if (!diag){
      #pragma unroll
      for (int i = 0; i < 2; i++){
        *reinterpret_cast<float4*>(cs + wid * TS + (i << 8) + (lane << 3))     = acc[2*i];
        *reinterpret_cast<float4*>(cs + wid * TS + (i << 8) + (lane << 3) + 4) = acc[2*i+1];
      }
      __syncthreads();
      for (int c = tid; c < TS; c += 256){
        float s = 0.f;
        #pragma unroll
        for (int w = 0; w < 8; w++) s += cs[w * TS + c];
        g_P[half][mat][B * TS + c][A] = s;
      }
    }
  } else {
    // ---------------- xy chain: half-row matvec, partial output ----------------
    int b2 = b - NSYMB;
    const __nv_bfloat16* K = even ? g_Kxy : g_Kyx;
    const float* win  = even ? g_wg : g_wf;
    float (*Pout)[2]  = even ? g_Pxy[0] : g_Pxy[1];
    int rowgrp = b2 >> 1, half = b2 & 1;
    int cbase = half << 12;

    float* sw = sbuf;   // 4096 w values for this column half
    for (int i = tid; i < 1024; i += 256)
      reinterpret_cast<float4*>(sw)[i] = reinterpret_cast<const float4*>(win + cbase)[i];
    __syncthreads();

    int row0 = (rowgrp << 4) + (wid << 1);
    const uint4* K0 = reinterpret_cast<const uint4*>(K + ((size_t)row0 << 13) + cbase);
    const uint4* K1 = reinterpret_cast<const uint4*>(K + ((size_t)(row0 + 1) << 13) + cbase);
    float s0 = 0.f, s1 = 0.f;
    #pragma unroll 4
    for (int it = lane; it < 512; it += 32){
      uint4 a = K0[it];
      uint4 c = K1[it];
      const float4* vp = reinterpret_cast<const float4*>(sw + (it << 3));
      float4 v0 = vp[0], v1 = vp[1];
      s0 += bf_lo(a.x)*v0.x + bf_hi(a.x)*v0.y + bf_lo(a.y)*v0.z + bf_hi(a.y)*v0.w
          + bf_lo(a.z)*v1.x + bf_hi(a.z)*v1.y + bf_lo(a.w)*v1.z + bf_hi(a.w)*v1.w;
      s1 += bf_lo(c.x)*v0.x + bf_hi(c.x)*v0.y + bf_lo(c.y)*v0.z + bf_hi(c.y)*v0.w
          + bf_lo(c.z)*v1.x + bf_hi(c.z)*v1.y + bf_lo(c.w)*v1.z + bf_hi(c.w)*v1.w;
    }
    #pragma unroll
    for (int o = 16; o; o >>= 1){
      s0 += __shfl_xor_sync(0xffffffffu, s0, o);
      s1 += __shfl_xor_sync(0xffffffffu, s1, o);
    }
    if (lane == 0){
      Pout[row0][half]     = s0;
      Pout[row0 + 1][half] = s1;
    }
  }
}

// Per-step reduce: xy partials (side of this step) + sym partials (both chains).
__global__ void __launch_bounds__(256) finish_kernel(int t){
  int idx = blockIdx.x * 256 + threadIdx.x;   // 0..24575
  int a = idx >> 13;                          // 0=xy, 1=hx, 2=hy
  int r = idx & (NPTS - 1);
  if (a == 0){
    int side = t & 1;                         // 0: f just written, 1: g
    float2 pp = *reinterpret_cast<const float2*>(g_Pxy[side][r]);
    float s = fmaxf(pp.x + pp.y, 1e-35f);
    float val = CLOGN - EPSV * __logf(s);
    if (side == 0){ g_f[r] = val; g_wf[r] = 8192.f / s; }
    else          { g_g[r] = val; g_wg[r] = 8192.f / s; }
  } else {
    int mat = a - 1;
    const float4* P0 = reinterpret_cast<const float4*>(&g_P[0][mat][r][0]);
    const float4* P1 = reinterpret_cast<const float4*>(&g_P[1][mat][r][0]);
    float4 a0 = P0[0], a1 = P0[1], a2 = P0[2], a3 = P0[3];
    float4 b0 = P1[0], b1 = P1[1], b2 = P1[2], b3 = P1[3];
    float s = (a0.x+a0.y+a0.z+a0.w) + (a1.x+a1.y+a1.z+a1.w)
            + (a2.x+a2.y+a2.z+a2.w) + (a3.x+a3.y+a3.z+a3.w)
            + (b0.x+b0.y+b0.z+b0.w) + (b1.x+b1.y+b1.z+b1.w)
            + (b2.x+b2.y+b2.z+b2.w) + (b3.x+b3.y+b3.z+b3.w);
    s = fmaxf(s, 1e-35f);
    float val = CLOGN - EPSV * __logf(s);
    int out = t & 1;
    if (mat == 0){ g_hx[out][r] = val; g_whx[out][r] = 8192.f / s; }
    else         { g_hy[out][r] = val; g_why[out][r] = 8192.f / s; }
  }
}

__global__ void final_kernel(float* out){
  __shared__ float sred[8];
  int tid = threadIdx.x, lane = tid & 31, wid = tid >> 5;
  const float* arrs[7] = { g_f, g_g, g_hx[0], g_hx[1], g_hy[0], g_hy[1], g_cham };
  float totals[7];
  for (int a = 0; a < 7; a++){
    float s = 0.f;
    for (int i = tid; i < NPTS; i += 256) s += arrs[a][i];
    #pragma unroll
    for (int o = 16; o; o >>= 1) s += __shfl_xor_sync(0xffffffffu, s, o);
    __syncthreads();
    if (lane == 0) sred[wid] = s;
    __syncthreads();
    if (tid == 0){
      float tt = 0.f;
      #pragma unroll
      for (int w = 0; w < 8; w++) tt += sred[w];
      totals[a] = tt;
    }
  }
  if (tid == 0){
    const float invN = 1.f / (float)NPTS;
    float ot_xy = (totals[0] + totals[1]) * invN;
    float ot_xx = (totals[2] + totals[3]) * invN;
    float ot_yy = (totals[4] + totals[5]) * invN;
    float cham  = totals[6] * invN;
    float emd = ot_xy - 0.5f * ot_xx - 0.5f * ot_yy;
    out[0] = 0.2f * cham + 0.8f * emd;
  }
}

extern "C" void kernel_launch(void* const* d_in, const int* in_sizes, int n_in,
                              void* d_out, int out_size){
  const float* pred = (const float*)d_in[0];
  const float* gt   = (const float*)d_in[1];
  float* out = (float*)d_out;

  setup_kernel<<<34048, 256>>>(pred, gt);   // init + all fills, one launch

  for (int t = 0; t < 100; t++){
    step_kernel<<<NSYMB + 1024, 256>>>(t);
    finish_kernel<<<96, 256>>>(t);
  }

  final_kernel<<<1, 256>>>(out);
}